// round 3
// baseline (speedup 1.0000x reference)
#include <cuda_runtime.h>
#include <cuda_bf16.h>

// Problem: B=8, T=128, D=256
//   E[p][q]      = exp(dec[b,p] * enc[b,t,q])
//   colsum[q]    = sum_p E[p][q]
//   rowsum[q]    = sum_c E[q][c]
//   out[b,q]     = sum_t enc[b,t,q] * colsum/rowsum
//
// R2: compute each E element ONCE (halves MUFU work vs R1).
// Warp w owns rows [32w,32w+32). Lane j: row p=32w+j, d fixed.
// Per 32-col tile, x=enc rotates via shfl; rowsum accumulates directly
// (lane-owned row); colsum uses an add-then-rotate accumulator whose 32
// rotations per tile compose to identity, leaving cs_j = sum_p E[p][c0+j].

#define B_DIM 8
#define T_DIM 128
#define D_DIM 256

__device__ __forceinline__ float ex2f(float x) {
    float y;
    asm("ex2.approx.ftz.f32 %0, %1;" : "=f"(y) : "f"(x));
    return y;
}

__global__ void zero_out_kernel(float* __restrict__ out, int n) {
    int i = blockIdx.x * blockDim.x + threadIdx.x;
    if (i < n) out[i] = 0.0f;
}

__global__ __launch_bounds__(D_DIM) void attn_ctx_kernel(
    const float* __restrict__ dec,   // [B, D]
    const float* __restrict__ enc,   // [B, T, D]
    float* __restrict__ out)         // [B, D]
{
    const int t = blockIdx.x;
    const int b = blockIdx.y;
    const int tid = threadIdx.x;
    const int w = tid >> 5;
    const int j = tid & 31;

    __shared__ float sdec[D_DIM];   // dec * log2(e)
    __shared__ float senc[D_DIM];   // enc row (b,t)
    __shared__ float srow[D_DIM];   // rowsum[p]
    __shared__ float scol[D_DIM];   // colsum[q] (accumulated across warps)

    const float LOG2E = 1.4426950408889634f;

    sdec[tid] = dec[b * D_DIM + tid] * LOG2E;
    float xq = enc[(b * T_DIM + t) * D_DIM + tid];
    senc[tid] = xq;
    scol[tid] = 0.0f;
    __syncthreads();

    const float d = sdec[w * 32 + j];   // this lane's fixed row operand
    const int jp1 = (j + 1) & 31;       // rotation source lane

    float rs = 0.0f;                    // rowsum[32w+j], direct accumulate

    for (int ct = 0; ct < 8; ++ct) {
        float x = senc[ct * 32 + j];    // column operand, rotates each step
        float cs = 0.0f;                // rotating colsum accumulator
        #pragma unroll
        for (int s = 0; s < 32; ++s) {
            float e = ex2f(d * x);
            rs += e;
            cs = __shfl_sync(0xffffffffu, cs + e, jp1);  // add-then-rotate
            x  = __shfl_sync(0xffffffffu, x, jp1);       // rotate column
        }
        // After 32 add-then-rotate steps: cs_j = sum over this warp's 32
        // rows of E[row][ct*32 + j]. Combine across warps.
        atomicAdd(&scol[ct * 32 + j], cs);
    }

    srow[w * 32 + j] = rs;  // single owner per row: plain store
    __syncthreads();

    // out[b,q] += enc[q] * colsum[q] / rowsum[q]
    atomicAdd(&out[b * D_DIM + tid], xq * scol[tid] / srow[tid]);
}

extern "C" void kernel_launch(void* const* d_in, const int* in_sizes, int n_in,
                              void* d_out, int out_size) {
    const float* dec = (const float*)d_in[0];   // [8, 256]
    const float* enc = (const float*)d_in[1];   // [8, 128, 256]
    float* out = (float*)d_out;                 // [8, 256]

    zero_out_kernel<<<(out_size + 255) / 256, 256>>>(out, out_size);

    dim3 grid(T_DIM, B_DIM);
    attn_ctx_kernel<<<grid, D_DIM>>>(dec, enc, out);
}

// round 5
// speedup vs baseline: 1.2810x; 1.2810x over previous
#include <cuda_runtime.h>
#include <cuda_bf16.h>

// Problem: B=8, T=128, D=256
//   E[p][q]   = exp(dec[b,p] * enc[b,t,q])
//   colsum[q] = sum_p E[p][q]
//   rowsum[p] = sum_q E[p][q]
//   out[b,q]  = sum_t enc[b,t,q] * colsum[q]/rowsum[q]
//
// R3: compute each E element ONCE (half the MUFU work of R1), with only
// 0.25 shuffles per exp (R2 used 2.0/exp and became MIO-bound).
//
// CTA = (b,t), 256 threads = 8 warps.
// Warp w owns column tile [32w, 32w+32) over ALL 256 rows.
// Lane j owns 8 rows {j + 32i}. Per rotation step: 8 exps, rowsums
// accumulate in registers (lane-owned rows); colsum uses add-then-rotate:
// cs and x rotate together each step, after 32 steps the rotation is the
// identity and cs_j = full colsum of column 32w+j (all 256 rows).

#define B_DIM 8
#define T_DIM 128
#define D_DIM 256

__device__ __forceinline__ float ex2f(float x) {
    float y;
    asm("ex2.approx.ftz.f32 %0, %1;" : "=f"(y) : "f"(x));
    return y;
}

__global__ void zero_out_kernel(float* __restrict__ out, int n) {
    int i = blockIdx.x * blockDim.x + threadIdx.x;
    if (i < n) out[i] = 0.0f;
}

__global__ __launch_bounds__(D_DIM) void attn_ctx_kernel(
    const float* __restrict__ dec,   // [B, D]
    const float* __restrict__ enc,   // [B, T, D]
    float* __restrict__ out)         // [B, D]
{
    const int t   = blockIdx.x;
    const int b   = blockIdx.y;
    const int tid = threadIdx.x;
    const int w   = tid >> 5;
    const int j   = tid & 31;

    __shared__ float sdec[D_DIM];   // dec * log2(e)
    __shared__ float senc[D_DIM];   // enc row (b,t)
    __shared__ float srow[D_DIM];   // rowsum[p], cross-warp accumulated
    __shared__ float scol[D_DIM];   // colsum[q]

    const float LOG2E = 1.4426950408889634f;

    sdec[tid] = dec[b * D_DIM + tid] * LOG2E;
    const float xq = enc[(b * T_DIM + t) * D_DIM + tid];
    senc[tid] = xq;
    srow[tid] = 0.0f;
    __syncthreads();

    // Lane j's 8 row operands (rows j, j+32, ..., j+224). Conflict-free LDS.
    float d[8], rs[8];
    #pragma unroll
    for (int i = 0; i < 8; ++i) {
        d[i]  = sdec[j + 32 * i];
        rs[i] = 0.0f;
    }

    const int jp1 = (j + 1) & 31;
    float x  = senc[w * 32 + j];    // column operand, rotates
    float cs = 0.0f;                // rotating colsum accumulator

    #pragma unroll 8
    for (int s = 0; s < 32; ++s) {
        float e0 = ex2f(d[0] * x);
        float e1 = ex2f(d[1] * x);
        float e2 = ex2f(d[2] * x);
        float e3 = ex2f(d[3] * x);
        float e4 = ex2f(d[4] * x);
        float e5 = ex2f(d[5] * x);
        float e6 = ex2f(d[6] * x);
        float e7 = ex2f(d[7] * x);
        rs[0] += e0; rs[1] += e1; rs[2] += e2; rs[3] += e3;
        rs[4] += e4; rs[5] += e5; rs[6] += e6; rs[7] += e7;
        float esum = ((e0 + e1) + (e2 + e3)) + ((e4 + e5) + (e6 + e7));
        cs = __shfl_sync(0xffffffffu, cs + esum, jp1);  // add-then-rotate
        x  = __shfl_sync(0xffffffffu, x, jp1);          // rotate column
    }

    // cs is now the COMPLETE colsum of column 32w+j (all 256 rows).
    scol[w * 32 + j] = cs;

    // Rowsum partials: this warp saw 32 of the 256 columns for each row.
    #pragma unroll
    for (int i = 0; i < 8; ++i)
        atomicAdd(&srow[j + 32 * i], rs[i]);   // spread addresses, cheap
    __syncthreads();

    // out[b,q] += enc[q] * colsum[q] / rowsum[q]
    atomicAdd(&out[b * D_DIM + tid], xq * scol[tid] / srow[tid]);
}

extern "C" void kernel_launch(void* const* d_in, const int* in_sizes, int n_in,
                              void* d_out, int out_size) {
    const float* dec = (const float*)d_in[0];   // [8, 256]
    const float* enc = (const float*)d_in[1];   // [8, 128, 256]
    float* out = (float*)d_out;                 // [8, 256]

    zero_out_kernel<<<(out_size + 255) / 256, 256>>>(out, out_size);

    dim3 grid(T_DIM, B_DIM);
    attn_ctx_kernel<<<grid, D_DIM>>>(dec, enc, out);
}

// round 6
// speedup vs baseline: 1.4349x; 1.1201x over previous
#include <cuda_runtime.h>
#include <cuda_bf16.h>

// Problem: B=8, T=128, D=256
//   E[p][q]   = exp(dec[b,p] * enc[b,t,q])
//   colsum[q] = sum_p E[p][q],  rowsum[p] = sum_q E[p][q]
//   out[b,q]  = sum_t enc[b,t,q] * colsum[q]/rowsum[q]
//
// R4: R3 structure (each E computed once, 0.25 shfl/exp), plus:
//  - all reduction adds as FFMA with immediate 1.0 multiplier (rt 1 on sm_103a)
//  - 1.5 of every 8 exps computed on the FMA pipe via polynomial ex2
//    (magic-round + deg-5 poly + ALU exponent insertion), offloading MUFU.
// Target: ~6.5 SMSP-cycles/exp vs the pure-MUFU floor of 8.

#define B_DIM 8
#define T_DIM 128
#define D_DIM 256

__device__ __forceinline__ float ex2f(float x) {
    float y;
    asm("ex2.approx.ftz.f32 %0, %1;" : "=f"(y) : "f"(x));
    return y;
}

// a + b as FFMA(a, 1.0_imm, b): imm-multiplier FFMA issues at rt 1 (vs 2).
__device__ __forceinline__ float addi(float a, float b) {
    float r;
    asm("fma.rn.f32 %0, %1, 0f3F800000, %2;" : "=f"(r) : "f"(a), "f"(b));
    return r;
}

// 2^z on the FMA/ALU pipes. |z| < 2^21. rel err ~3e-6.
__device__ __forceinline__ float ex2p(float z) {
    const float MAGIC = 12582912.0f;            // 2^23 + 2^22
    float t, t2, f;
    // t = z + MAGIC (round-to-nearest-int captured in mantissa)
    asm("fma.rn.f32 %0, %1, 0f3F800000, %2;" : "=f"(t)  : "f"(z), "f"(MAGIC));
    // t2 = t - MAGIC  (= rounded integer part n)
    asm("fma.rn.f32 %0, %1, 0f3F800000, %2;" : "=f"(t2) : "f"(t), "f"(-MAGIC));
    // f = z - n, f in [-0.5, 0.5]
    asm("fma.rn.f32 %0, %1, 0fBF800000, %2;" : "=f"(f)  : "f"(t2), "f"(z));
    // low mantissa bits of t hold n (two's complement); magic's low 9 bits are 0
    int eb = __float_as_int(t) << 23;           // n * 2^23 (mod 2^32)
    // 2^f, Taylor deg 5 (coeffs ln2^k/k!)
    float p;
    p = __fmaf_rn(0.00133335581f, f, 0.00961812911f);
    p = __fmaf_rn(p, f, 0.0555041087f);
    p = __fmaf_rn(p, f, 0.240226507f);
    p = __fmaf_rn(p, f, 0.693147181f);
    p = __fmaf_rn(p, f, 1.0f);
    // scale by 2^n via exponent-field add (ALU pipe)
    return __int_as_float(__float_as_int(p) + eb);
}

__global__ void zero_out_kernel(float* __restrict__ out, int n) {
    int i = blockIdx.x * blockDim.x + threadIdx.x;
    if (i < n) out[i] = 0.0f;
}

__global__ __launch_bounds__(D_DIM) void attn_ctx_kernel(
    const float* __restrict__ dec,   // [B, D]
    const float* __restrict__ enc,   // [B, T, D]
    float* __restrict__ out)         // [B, D]
{
    const int t   = blockIdx.x;
    const int b   = blockIdx.y;
    const int tid = threadIdx.x;
    const int w   = tid >> 5;
    const int j   = tid & 31;

    __shared__ float sdec[D_DIM];   // dec * log2(e)
    __shared__ float senc[D_DIM];   // enc row (b,t)
    __shared__ float srow[D_DIM];   // rowsum[p], cross-warp accumulated
    __shared__ float scol[D_DIM];   // colsum[q]

    const float LOG2E = 1.4426950408889634f;

    sdec[tid] = dec[b * D_DIM + tid] * LOG2E;
    const float xq = enc[(b * T_DIM + t) * D_DIM + tid];
    senc[tid] = xq;
    srow[tid] = 0.0f;
    __syncthreads();

    // Lane j's 8 row operands (rows j, j+32, ..., j+224). Conflict-free LDS.
    float d[8], rs[8];
    #pragma unroll
    for (int i = 0; i < 8; ++i) {
        d[i]  = sdec[j + 32 * i];
        rs[i] = 0.0f;
    }

    const int jp1 = (j + 1) & 31;
    float x  = senc[w * 32 + j];    // column operand, rotates
    float cs = 0.0f;                // rotating colsum accumulator

    for (int so = 0; so < 4; ++so) {
        #pragma unroll
        for (int si = 0; si < 8; ++si) {
            // 6 or 7 exps on MUFU, 1.5 avg on the FMA-pipe polynomial
            float e0 = ex2f(d[0] * x);
            float e1 = ex2f(d[1] * x);
            float e2 = ex2f(d[2] * x);
            float e3 = ex2f(d[3] * x);
            float e4 = ex2f(d[4] * x);
            float e5 = ex2f(d[5] * x);
            float e6 = ((si & 1) == 0) ? ex2p(d[6] * x) : ex2f(d[6] * x);
            float e7 = ex2p(d[7] * x);

            rs[0] = addi(e0, rs[0]);
            rs[1] = addi(e1, rs[1]);
            rs[2] = addi(e2, rs[2]);
            rs[3] = addi(e3, rs[3]);
            rs[4] = addi(e4, rs[4]);
            rs[5] = addi(e5, rs[5]);
            rs[6] = addi(e6, rs[6]);
            rs[7] = addi(e7, rs[7]);

            float s01 = addi(e0, e1);
            float s23 = addi(e2, e3);
            float s45 = addi(e4, e5);
            float s67 = addi(e6, e7);
            float s03 = addi(s01, s23);
            float s47 = addi(s45, s67);
            float esum = addi(s03, s47);

            cs = __shfl_sync(0xffffffffu, addi(cs, esum), jp1);  // add-then-rotate
            x  = __shfl_sync(0xffffffffu, x, jp1);               // rotate column
        }
    }

    // cs is the COMPLETE colsum of column 32w+j (all 256 rows).
    scol[w * 32 + j] = cs;

    // Rowsum partials: this warp saw 32 of the 256 columns for each row.
    #pragma unroll
    for (int i = 0; i < 8; ++i)
        atomicAdd(&srow[j + 32 * i], rs[i]);   // spread addresses, cheap
    __syncthreads();

    // out[b,q] += enc[q] * colsum[q] / rowsum[q]
    atomicAdd(&out[b * D_DIM + tid], xq * scol[tid] / srow[tid]);
}

extern "C" void kernel_launch(void* const* d_in, const int* in_sizes, int n_in,
                              void* d_out, int out_size) {
    const float* dec = (const float*)d_in[0];   // [8, 256]
    const float* enc = (const float*)d_in[1];   // [8, 128, 256]
    float* out = (float*)d_out;                 // [8, 256]

    zero_out_kernel<<<(out_size + 255) / 256, 256>>>(out, out_size);

    dim3 grid(T_DIM, B_DIM);
    attn_ctx_kernel<<<grid, D_DIM>>>(dec, enc, out);
}